// round 13
// baseline (speedup 1.0000x reference)
#include <cuda_runtime.h>
#include <cuda_fp16.h>
#include <math.h>
#include <stdint.h>

#define B_ 32768
#define M_ 10
#define BM_ (B_*M_)

// fp16 scratch (allocation-free rule: __device__ globals)
__device__ __align__(128) __half g_prevh[(size_t)BM_ * 256];
__device__ __align__(128) __half g_curh [(size_t)B_ * 256];
__device__ __align__(128) __half g_w16  [655360];            // 8 slots 256x256 + Wo 512x256, k-paired
__device__ __align__(128) __half g_curxh[(size_t)B_ * 1024]; // [z|r|h|q] pre-acts per batch
__device__ __align__(128) __half g_zh   [(size_t)BM_ * 256];
__device__ __align__(128) __half g_rph  [(size_t)BM_ * 256];
__device__ __align__(128) __half g_updh [(size_t)BM_ * 256];
__device__ __align__(128) __half g_xh   [(size_t)B_ * 512];  // [cur | weighted]
__device__ float g_scores[(size_t)B_ * 80];
__device__ float g_f[(size_t)B_ * 256];

__device__ __forceinline__ float sigmoidf_(float x) { return 1.f / (1.f + expf(-x)); }
__device__ __forceinline__ float2 h2f(__half2 h) { return __half22float2(h); }

__device__ __forceinline__ uint32_t smem_u32(const void* p) {
    return (uint32_t)__cvta_generic_to_shared(p);
}
__device__ __forceinline__ void cp_async16(uint32_t s, const void* g) {
    asm volatile("cp.async.cg.shared.global [%0], [%1], 16;\n" :: "r"(s), "l"(g));
}
__device__ __forceinline__ void cp_commit() {
    asm volatile("cp.async.commit_group;\n");
}
template<int N>
__device__ __forceinline__ void cp_wait() {
    asm volatile("cp.async.wait_group %0;\n" :: "n"(N));
}

__device__ __forceinline__ void mma_f16(float c[4], const uint32_t a[4], const uint32_t b[2]) {
    asm volatile(
        "mma.sync.aligned.m16n8k16.row.col.f32.f16.f16.f32 "
        "{%0,%1,%2,%3}, {%4,%5,%6,%7}, {%8,%9}, {%0,%1,%2,%3};"
        : "+f"(c[0]), "+f"(c[1]), "+f"(c[2]), "+f"(c[3])
        : "r"(a[0]), "r"(a[1]), "r"(a[2]), "r"(a[3]), "r"(b[0]), "r"(b[1]));
}

// ===========================================================================
// prep kernels (unchanged from round 12)
// ===========================================================================
__global__ __launch_bounds__(256)
void prep_inputs(const float* __restrict__ prev, const float* __restrict__ cur)
{
    const size_t NP = (size_t)BM_ * 256 / 8;
    const size_t NC = (size_t)B_ * 256 / 8;
    size_t i = (size_t)blockIdx.x * 256 + threadIdx.x;
    if (i < NP) {
        size_t off = i * 8;
        float4 f0 = *(const float4*)(prev + off);
        float4 f1 = *(const float4*)(prev + off + 4);
        *(__half2*)(g_prevh + off + 0) = __floats2half2_rn(f0.x, f0.y);
        *(__half2*)(g_prevh + off + 2) = __floats2half2_rn(f0.z, f0.w);
        *(__half2*)(g_prevh + off + 4) = __floats2half2_rn(f1.x, f1.y);
        *(__half2*)(g_prevh + off + 6) = __floats2half2_rn(f1.z, f1.w);
    } else if (i < NP + NC) {
        size_t off = (i - NP) * 8;
        float4 f0 = *(const float4*)(cur + off);
        float4 f1 = *(const float4*)(cur + off + 4);
        __half2 h0 = __floats2half2_rn(f0.x, f0.y), h1 = __floats2half2_rn(f0.z, f0.w);
        __half2 h2 = __floats2half2_rn(f1.x, f1.y), h3 = __floats2half2_rn(f1.z, f1.w);
        *(__half2*)(g_curh + off + 0) = h0;  *(__half2*)(g_curh + off + 2) = h1;
        *(__half2*)(g_curh + off + 4) = h2;  *(__half2*)(g_curh + off + 6) = h3;
        size_t b = off >> 8, c = off & 255;
        __half* xd = g_xh + b * 512 + c;
        *(__half2*)(xd + 0) = h0;  *(__half2*)(xd + 2) = h1;
        *(__half2*)(xd + 4) = h2;  *(__half2*)(xd + 6) = h3;
    }
}

// k-paired layout: (k,n) at slot*65536 + (k>>1)*512 + n*2 + (k&1)
__global__ __launch_bounds__(256)
void prep_weights(const float* __restrict__ Wz, const float* __restrict__ Wr,
                  const float* __restrict__ Wh, const float* __restrict__ Wq,
                  const float* __restrict__ Wk, const float* __restrict__ Wo)
{
    const int blk = blockIdx.z;
    const float* src; size_t slot; int K;
    switch (blk) {
        case 0: src = Wz;         slot = 0; K = 256; break;
        case 1: src = Wr;         slot = 1; K = 256; break;
        case 2: src = Wh;         slot = 2; K = 256; break;
        case 3: src = Wq;         slot = 3; K = 256; break;
        case 4: src = Wz + 65536; slot = 4; K = 256; break;
        case 5: src = Wr + 65536; slot = 5; K = 256; break;
        case 6: src = Wh + 65536; slot = 6; K = 256; break;
        case 7: src = Wk;         slot = 7; K = 256; break;
        default: src = Wo;        slot = 8; K = 512; break;
    }
    int n = blockIdx.x * 32 + (threadIdx.x & 31);
    int k = blockIdx.y * 8 + (threadIdx.x >> 5);
    if (k >= K) return;
    g_w16[slot * 65536 + (size_t)(k >> 1) * 512 + n * 2 + (k & 1)] =
        __float2half(src[(size_t)k * 256 + n]);
}

// ===========================================================================
// fp16 GEMM. Modes 0-3: persistent-B (full K=256 x 128-col weight tile in smem),
// MT=4 m-tiles per CTA, flat 32-chunk A stream (K-chunk 32 halves), 3 A buffers,
// one barrier per chunk, epilogue per m-tile. MODE 4: round-12 streaming (K=512).
// 256 threads, 8 warps 2m x 4n, warp tile 64x32, mma m16n8k16, 2 CTAs/SM.
// ===========================================================================
#define AH2P 20                    // A words/row per 32-half chunk (16 + pad 4)
#define ACHP (128 * AH2P)          // 2560 words per A buffer
#define BRES (128 * 136)           // 17408 words: 128 k2-rows x (128 n + pad 8)
#define PSMEM ((BRES + 3 * ACHP) * 4)          // 100352 B
#define AH24 36
#define BH24 136
#define BUF4 (128 * AH24 + 32 * BH24)          // mode-4 streaming buffer (words)
#define M4SMEM (3 * BUF4 * 4)                  // 107520 B
#define MT 4

template<int MODE>
__global__ __launch_bounds__(256, 2)
void mma_gemm(const float* __restrict__ ba, const float* __restrict__ bb,
              const float* __restrict__ bc, const float* __restrict__ bd,
              float* __restrict__ out)
{
    extern __shared__ __align__(16) uint32_t smh[];

    const int tid  = threadIdx.x;
    const int lane = tid & 31;
    const int warp = tid >> 5;
    const int wm   = warp >> 2;
    const int wn   = warp & 3;
    const int q    = lane >> 2;
    const int t4   = lane & 3;

    const int n0  = blockIdx.x * 128;
    const int seg = n0 >> 8;
    const int ncol = n0 & 255;

    const __half* Ap = (MODE == 0) ? g_curh : (MODE == 1) ? g_prevh
                     : (MODE == 2) ? g_rph  : (MODE == 3) ? g_updh : g_xh;
    const int slot = (MODE == 0) ? seg : (MODE == 1) ? 4 + seg
                   : (MODE == 2) ? 6 : (MODE == 3) ? 7 : 8;
    const __half* Wsrc = g_w16 + (size_t)slot * 65536;
    const float* bias = (seg == 0) ? ba : (seg == 1) ? bb : (seg == 2) ? bc : bd;

    float acc[4][4][4];
    #pragma unroll
    for (int i = 0; i < 4; i++)
        #pragma unroll
        for (int j = 0; j < 4; j++)
            #pragma unroll
            for (int v = 0; v < 4; v++) acc[i][j][v] = 0.f;

    // --------------- epilogue for one 128-row m-tile (modes 0-3) -----------
    auto epilogue = [&](int m0) {
        if (MODE == 3) {
            const int head = (n0 >> 5) + wn;
            #pragma unroll
            for (int mt = 0; mt < 4; mt++) {
                #pragma unroll
                for (int half = 0; half < 2; half++) {
                    const int row = m0 + wm * 64 + mt * 16 + q + half * 8;
                    const int b = row / 10, m = row - b * 10;
                    const __half* qp = g_curxh + (size_t)b * 1024 + 768;
                    float s = 0.f;
                    #pragma unroll
                    for (int nt = 0; nt < 4; nt++) {
                        const int col = n0 + wn * 32 + nt * 8 + 2 * t4;
                        float2 bk2 = *(const float2*)(ba + col);
                        float2 qv  = h2f(*(const __half2*)(qp + col));
                        s += (acc[mt][nt][half * 2 + 0] + bk2.x) * qv.x
                           + (acc[mt][nt][half * 2 + 1] + bk2.y) * qv.y;
                    }
                    s += __shfl_xor_sync(0xffffffffu, s, 1);
                    s += __shfl_xor_sync(0xffffffffu, s, 2);
                    if (t4 == 0)
                        g_scores[((size_t)b * 8 + head) * 10 + m] = s;
                }
            }
            return;
        }
        #pragma unroll
        for (int mt = 0; mt < 4; mt++) {
            #pragma unroll
            for (int nt = 0; nt < 4; nt++) {
                const int h = ncol + wn * 32 + nt * 8 + 2 * t4;
                #pragma unroll
                for (int half = 0; half < 2; half++) {
                    const int row = m0 + wm * 64 + mt * 16 + q + half * 8;
                    const float v0 = acc[mt][nt][half * 2 + 0];
                    const float v1 = acc[mt][nt][half * 2 + 1];
                    if (MODE == 0) {
                        float2 bb2 = *(const float2*)(bias + h);
                        *(__half2*)(g_curxh + (size_t)row * 1024 + seg * 256 + h) =
                            __floats2half2_rn(v0 + bb2.x, v1 + bb2.y);
                    } else if (MODE == 1) {
                        const int b = row / 10;
                        if (seg == 0) {
                            float2 cx = h2f(*(const __half2*)(g_curxh + (size_t)b * 1024 + h));
                            *(__half2*)(g_zh + (size_t)row * 256 + h) =
                                __floats2half2_rn(sigmoidf_(v0 + cx.x), sigmoidf_(v1 + cx.y));
                        } else {
                            float2 cx = h2f(*(const __half2*)(g_curxh + (size_t)b * 1024 + 256 + h));
                            float2 pv = h2f(*(const __half2*)(g_prevh + (size_t)row * 256 + h));
                            *(__half2*)(g_rph + (size_t)row * 256 + h) =
                                __floats2half2_rn(sigmoidf_(v0 + cx.x) * pv.x,
                                                  sigmoidf_(v1 + cx.y) * pv.y);
                        }
                    } else if (MODE == 2) {
                        const int b = row / 10;
                        float2 cx = h2f(*(const __half2*)(g_curxh + (size_t)b * 1024 + 512 + h));
                        float2 zz = h2f(*(const __half2*)(g_zh + (size_t)row * 256 + h));
                        float2 pv = h2f(*(const __half2*)(g_prevh + (size_t)row * 256 + h));
                        float c0 = tanhf(v0 + cx.x), c1 = tanhf(v1 + cx.y);
                        float u0 = (1.f - zz.x) * pv.x + zz.x * c0;
                        float u1 = (1.f - zz.y) * pv.y + zz.y * c1;
                        *(float2*)(out + (size_t)row * 256 + h) = make_float2(u0, u1);
                        *(__half2*)(g_updh + (size_t)row * 256 + h) = __floats2half2_rn(u0, u1);
                    } else {  // MODE 4
                        float2 bb2 = *(const float2*)(ba + h);
                        *(float2*)(g_f + (size_t)row * 256 + h) =
                            make_float2(v0 + bb2.x, v1 + bb2.y);
                    }
                }
            }
        }
    };

    if constexpr (MODE != 4) {
        // ---------------- persistent-B multi-m-tile path ----------------
        const int mbase = blockIdx.y * (128 * MT);
        uint32_t* Bres = smh;
        uint32_t* Ab0  = smh + BRES;

        // Load full B tile (K=256 -> 128 k2-rows x 128 cols), ONE commit group.
        #pragma unroll
        for (int i = 0; i < 16; i++) {
            int g = i * 256 + tid;
            int k2 = g >> 5, w4 = (g & 31) << 2;
            cp_async16(smem_u32(Bres + k2 * 136 + w4),
                       Wsrc + (size_t)k2 * 512 + (ncol + w4) * 2);
        }
        cp_commit();

        auto loadA = [&](int cs) {
            uint32_t* Ad = Ab0 + (cs % 3) * ACHP;
            const __half* Asrc = Ap + (size_t)(mbase + (cs >> 3) * 128) * 256 + (cs & 7) * 32;
            #pragma unroll
            for (int i = 0; i < 2; i++) {
                int g = i * 256 + tid;
                int row = g >> 2, gr = g & 3;
                cp_async16(smem_u32(Ad + row * AH2P + gr * 4),
                           Asrc + (size_t)row * 256 + gr * 8);
            }
            cp_commit();
        };

        loadA(0);
        loadA(1);

        #pragma unroll 1
        for (int cs = 0; cs < 8 * MT; cs++) {
            if (cs < 8 * MT - 1) cp_wait<1>(); else cp_wait<0>();
            __syncthreads();
            // buffer (cs+2)%3 was consumed at iter cs-1; barrier makes reuse safe
            if (cs + 2 < 8 * MT) loadA(cs + 2);

            const uint32_t* Ah = Ab0 + (cs % 3) * ACHP;
            const int kc = cs & 7;
            #pragma unroll
            for (int kk = 0; kk < 2; kk++) {
                uint32_t a[4][4], b[4][2];
                const int ac = kk * 8 + t4;
                const int kb = kc * 16 + kk * 8 + t4;
                #pragma unroll
                for (int mt = 0; mt < 4; mt++) {
                    const int r0 = wm * 64 + mt * 16 + q;
                    a[mt][0] = Ah[r0 * AH2P + ac];
                    a[mt][1] = Ah[(r0 + 8) * AH2P + ac];
                    a[mt][2] = Ah[r0 * AH2P + ac + 4];
                    a[mt][3] = Ah[(r0 + 8) * AH2P + ac + 4];
                }
                #pragma unroll
                for (int nt = 0; nt < 4; nt++) {
                    const int nb = wn * 32 + nt * 8 + q;
                    b[nt][0] = Bres[kb * 136 + nb];
                    b[nt][1] = Bres[(kb + 4) * 136 + nb];
                }
                #pragma unroll
                for (int mt = 0; mt < 4; mt++)
                    #pragma unroll
                    for (int nt = 0; nt < 4; nt++)
                        mma_f16(acc[mt][nt], a[mt], b[nt]);
            }

            if ((cs & 7) == 7) {
                epilogue(mbase + (cs >> 3) * 128);
                #pragma unroll
                for (int i = 0; i < 4; i++)
                    #pragma unroll
                    for (int j = 0; j < 4; j++)
                        #pragma unroll
                        for (int v = 0; v < 4; v++) acc[i][j][v] = 0.f;
            }
        }
    } else {
        // ---------------- MODE 4: round-12 streaming path (K=512) ----------------
        const int m0 = blockIdx.y * 128;
        auto load_chunk = [&](int bi, int k0) {
            uint32_t* Ad = smh + bi * BUF4;
            uint32_t* Bd = Ad + 128 * AH24;
            #pragma unroll
            for (int i = 0; i < 4; i++) {
                int g = i * 256 + tid;
                int m = g >> 3, c8 = g & 7;
                cp_async16(smem_u32(Ad + m * AH24 + c8 * 4),
                           Ap + (size_t)(m0 + m) * 512 + k0 + c8 * 8);
            }
            #pragma unroll
            for (int i = 0; i < 4; i++) {
                int g = i * 256 + tid;
                int k2 = g >> 5, n4 = (g & 31) << 2;
                cp_async16(smem_u32(Bd + k2 * BH24 + n4),
                           Wsrc + ((size_t)(k0 >> 1) + k2) * 512 + (ncol + n4) * 2);
            }
            cp_commit();
        };

        load_chunk(0, 0);
        load_chunk(1, 64);

        #pragma unroll
        for (int c = 0; c < 8; c++) {
            if (c < 7) cp_wait<1>(); else cp_wait<0>();
            __syncthreads();
            if (c + 2 < 8) load_chunk((c + 2) % 3, (c + 2) * 64);

            const uint32_t* Ah = smh + (c % 3) * BUF4;
            const uint32_t* Bh = Ah + 128 * AH24;
            #pragma unroll
            for (int kk = 0; kk < 4; kk++) {
                uint32_t a[4][4], b[4][2];
                const int ac = kk * 8 + t4;
                #pragma unroll
                for (int mt = 0; mt < 4; mt++) {
                    const int r0 = wm * 64 + mt * 16 + q;
                    a[mt][0] = Ah[r0 * AH24 + ac];
                    a[mt][1] = Ah[(r0 + 8) * AH24 + ac];
                    a[mt][2] = Ah[r0 * AH24 + ac + 4];
                    a[mt][3] = Ah[(r0 + 8) * AH24 + ac + 4];
                }
                #pragma unroll
                for (int nt = 0; nt < 4; nt++) {
                    const int nb = wn * 32 + nt * 8 + q;
                    b[nt][0] = Bh[ac * BH24 + nb];
                    b[nt][1] = Bh[(ac + 4) * BH24 + nb];
                }
                #pragma unroll
                for (int mt = 0; mt < 4; mt++)
                    #pragma unroll
                    for (int nt = 0; nt < 4; nt++)
                        mma_f16(acc[mt][nt], a[mt], b[nt]);
            }
        }
        epilogue(m0);
    }
}

// ---------------------------------------------------------------------------
// attn_light (unchanged from round 12)
// ---------------------------------------------------------------------------
#define GB_ 32

__global__ __launch_bounds__(256)
void attn_light(float* __restrict__ d_out)
{
    __shared__ float ss[GB_ * 80];
    __shared__ float sattn[GB_ * 10];

    const int tid = threadIdx.x;
    const int b0 = blockIdx.x * GB_;
    float* attn_out = d_out + (size_t)B_ * 256 + (size_t)BM_ * 256;

    const float scale = 0.17677669529663687f;
    for (int t = tid; t < GB_ * 80; t += 256)
        ss[t] = g_scores[(size_t)b0 * 80 + t] * scale;
    __syncthreads();

    for (int t = tid; t < GB_ * 8; t += 256) {
        float* row = ss + t * 10;
        float mx = row[0];
        #pragma unroll
        for (int m = 1; m < 10; m++) mx = fmaxf(mx, row[m]);
        float e[10], sum = 0.f;
        #pragma unroll
        for (int m = 0; m < 10; m++) { e[m] = expf(row[m] - mx); sum += e[m]; }
        float inv = 1.f / sum;
        #pragma unroll
        for (int m = 0; m < 10; m++) row[m] = e[m] * inv;
    }
    __syncthreads();

    for (int t = tid; t < GB_ * 10; t += 256) {
        int bi = t / 10, m = t % 10;
        float s = 0.f;
        #pragma unroll
        for (int n = 0; n < 8; n++) s += ss[(bi * 8 + n) * 10 + m];
        s *= 0.125f;
        sattn[t] = s;
        attn_out[(size_t)(b0 + bi) * 10 + m] = s;
    }
    __syncthreads();

    for (int idx = tid; idx < GB_ * 32; idx += 256) {
        int bi = idx >> 5, g8 = idx & 31;
        const __half2* up = (const __half2*)(g_updh + ((size_t)(b0 + bi) * 10) * 256) + g8 * 4;
        const float* aw = sattn + bi * 10;
        float2 s0 = {0.f, 0.f}, s1 = {0.f, 0.f}, s2 = {0.f, 0.f}, s3 = {0.f, 0.f};
        #pragma unroll
        for (int m = 0; m < 10; m++) {
            float w = aw[m];
            float2 u0 = h2f(up[m * 128 + 0]);
            float2 u1 = h2f(up[m * 128 + 1]);
            float2 u2 = h2f(up[m * 128 + 2]);
            float2 u3 = h2f(up[m * 128 + 3]);
            s0.x += u0.x * w; s0.y += u0.y * w;
            s1.x += u1.x * w; s1.y += u1.y * w;
            s2.x += u2.x * w; s2.y += u2.y * w;
            s3.x += u3.x * w; s3.y += u3.y * w;
        }
        __half2* xw = (__half2*)(g_xh + (size_t)(b0 + bi) * 512 + 256) + g8 * 4;
        xw[0] = __floats2half2_rn(s0.x, s0.y);
        xw[1] = __floats2half2_rn(s1.x, s1.y);
        xw[2] = __floats2half2_rn(s2.x, s2.y);
        xw[3] = __floats2half2_rn(s3.x, s3.y);
    }
}

// ---------------------------------------------------------------------------
// LayerNorm over g_f -> d_out.
// ---------------------------------------------------------------------------
__global__ __launch_bounds__(256)
void ln_kernel(const float* __restrict__ gamma, const float* __restrict__ beta,
               float* __restrict__ d_out)
{
    const int warp = threadIdx.x >> 5;
    const int lane = threadIdx.x & 31;
    const int row  = blockIdx.x * 8 + warp;

    float v[8], sum = 0.f;
    const float* src = g_f + (size_t)row * 256;
    #pragma unroll
    for (int i = 0; i < 8; i++) { v[i] = src[lane + 32 * i]; sum += v[i]; }
    #pragma unroll
    for (int o = 16; o > 0; o >>= 1) sum += __shfl_xor_sync(0xffffffffu, sum, o);
    float mu = sum * (1.f / 256.f);
    float sq = 0.f;
    #pragma unroll
    for (int i = 0; i < 8; i++) { float d = v[i] - mu; sq += d * d; }
    #pragma unroll
    for (int o = 16; o > 0; o >>= 1) sq += __shfl_xor_sync(0xffffffffu, sq, o);
    float rstd = rsqrtf(sq * (1.f / 256.f) + 1e-5f);
    float* dst = d_out + (size_t)row * 256;
    #pragma unroll
    for (int i = 0; i < 8; i++) {
        int d_ = lane + 32 * i;
        dst[d_] = (v[i] - mu) * rstd * gamma[d_] + beta[d_];
    }
}

extern "C" void kernel_launch(void* const* d_in, const int* in_sizes, int n_in,
                              void* d_out, int out_size)
{
    (void)in_sizes; (void)n_in; (void)out_size;
    const float* cur    = (const float*)d_in[0];
    const float* prev   = (const float*)d_in[1];
    const float* Wz     = (const float*)d_in[2];
    const float* bz     = (const float*)d_in[3];
    const float* Wr     = (const float*)d_in[4];
    const float* br     = (const float*)d_in[5];
    const float* Wh     = (const float*)d_in[6];
    const float* bh     = (const float*)d_in[7];
    const float* Wq     = (const float*)d_in[8];
    const float* bq     = (const float*)d_in[9];
    const float* Wk     = (const float*)d_in[10];
    const float* bk     = (const float*)d_in[11];
    const float* Wo     = (const float*)d_in[12];
    const float* bo     = (const float*)d_in[13];
    const float* gamma2 = (const float*)d_in[14];
    const float* beta2  = (const float*)d_in[15];
    float* out = (float*)d_out;
    float* upd = out + (size_t)B_ * 256;

    cudaFuncSetAttribute(mma_gemm<0>, cudaFuncAttributeMaxDynamicSharedMemorySize, (int)PSMEM);
    cudaFuncSetAttribute(mma_gemm<1>, cudaFuncAttributeMaxDynamicSharedMemorySize, (int)PSMEM);
    cudaFuncSetAttribute(mma_gemm<2>, cudaFuncAttributeMaxDynamicSharedMemorySize, (int)PSMEM);
    cudaFuncSetAttribute(mma_gemm<3>, cudaFuncAttributeMaxDynamicSharedMemorySize, (int)PSMEM);
    cudaFuncSetAttribute(mma_gemm<4>, cudaFuncAttributeMaxDynamicSharedMemorySize, (int)M4SMEM);

    dim3 blk(256);
    const int NPREP = (int)(((size_t)BM_ * 256 / 8 + (size_t)B_ * 256 / 8 + 255) / 256);
    // 0) convert inputs + weights to fp16
    prep_inputs<<<NPREP, blk>>>(prev, cur);
    prep_weights<<<dim3(8, 64, 9), blk>>>(Wz, Wr, Wh, Wq, Wk, Wo);
    // 1) cur projections: [B,256] @ [256,1024]  (8 n-tiles, 512 rows/CTA)
    mma_gemm<0><<<dim3(8, B_ / 512), blk, PSMEM>>>(bz, br, bh, bq, nullptr);
    // 2) z/r gates: [BM,256] @ [256,512]
    mma_gemm<1><<<dim3(4, BM_ / 512), blk, PSMEM>>>(nullptr, nullptr, nullptr, nullptr, nullptr);
    // 3) cand + GRU update -> updated_memory (+ fp16 copy)
    mma_gemm<2><<<dim3(2, BM_ / 512), blk, PSMEM>>>(nullptr, nullptr, nullptr, nullptr, upd);
    // 4) k projection + fused attention scores -> g_scores
    mma_gemm<3><<<dim3(2, BM_ / 512), blk, PSMEM>>>(bk, nullptr, nullptr, nullptr, nullptr);
    // 5) softmax/head-mean/weighted -> g_xh, attn weights
    attn_light<<<dim3(B_ / GB_), blk>>>(out);
    // 6) output projection: [B,512] @ [512,256] -> g_f
    mma_gemm<4><<<dim3(2, B_ / 128), blk, M4SMEM>>>(bo, nullptr, nullptr, nullptr, nullptr);
    // 7) LayerNorm -> d_out
    ln_kernel<<<dim3(B_ / 8), blk>>>(gamma2, beta2, out);
}

// round 14
// speedup vs baseline: 1.2254x; 1.2254x over previous
#include <cuda_runtime.h>
#include <cuda_fp16.h>
#include <math.h>
#include <stdint.h>

#define B_ 32768
#define M_ 10
#define BM_ (B_*M_)

// fp16 scratch (allocation-free rule: __device__ globals)
__device__ __align__(128) __half g_prevh[(size_t)BM_ * 256];
__device__ __align__(128) __half g_curh [(size_t)B_ * 256];
__device__ __align__(128) __half g_w16  [655360];            // 8 slots 256x256 + Wo 512x256, k-paired
__device__ __align__(128) __half g_curxh[(size_t)B_ * 1024]; // [z|r|h|q] pre-acts per batch
__device__ __align__(128) __half g_zh   [(size_t)BM_ * 256];
__device__ __align__(128) __half g_rph  [(size_t)BM_ * 256];
__device__ __align__(128) __half g_updh [(size_t)BM_ * 256];
__device__ __align__(128) __half g_xh   [(size_t)B_ * 512];  // [cur | weighted]
__device__ float g_scores[(size_t)B_ * 80];
__device__ float g_f[(size_t)B_ * 256];

// fast-math activations (MUFU-based; error ~1e-6 rel, far below fp16 storage quantum)
__device__ __forceinline__ float sigmoidf_(float x) {
    return __fdividef(1.f, 1.f + __expf(-x));
}
__device__ __forceinline__ float tanhf_(float x) {
    float t = __expf(-2.f * fabsf(x));            // in (0,1], no overflow
    float r = __fdividef(1.f - t, 1.f + t);
    return copysignf(r, x);
}
__device__ __forceinline__ float2 h2f(__half2 h) { return __half22float2(h); }

__device__ __forceinline__ uint32_t smem_u32(const void* p) {
    return (uint32_t)__cvta_generic_to_shared(p);
}
__device__ __forceinline__ void cp_async16(uint32_t s, const void* g) {
    asm volatile("cp.async.cg.shared.global [%0], [%1], 16;\n" :: "r"(s), "l"(g));
}
__device__ __forceinline__ void cp_commit() {
    asm volatile("cp.async.commit_group;\n");
}
template<int N>
__device__ __forceinline__ void cp_wait() {
    asm volatile("cp.async.wait_group %0;\n" :: "n"(N));
}

__device__ __forceinline__ void mma_f16(float c[4], const uint32_t a[4], const uint32_t b[2]) {
    asm volatile(
        "mma.sync.aligned.m16n8k16.row.col.f32.f16.f16.f32 "
        "{%0,%1,%2,%3}, {%4,%5,%6,%7}, {%8,%9}, {%0,%1,%2,%3};"
        : "+f"(c[0]), "+f"(c[1]), "+f"(c[2]), "+f"(c[3])
        : "r"(a[0]), "r"(a[1]), "r"(a[2]), "r"(a[3]), "r"(b[0]), "r"(b[1]));
}

// ===========================================================================
// prep_inputs: prev, cur -> fp16; also seed g_xh cur-section.
// ===========================================================================
__global__ __launch_bounds__(256)
void prep_inputs(const float* __restrict__ prev, const float* __restrict__ cur)
{
    const size_t NP = (size_t)BM_ * 256 / 8;
    const size_t NC = (size_t)B_ * 256 / 8;
    size_t i = (size_t)blockIdx.x * 256 + threadIdx.x;
    if (i < NP) {
        size_t off = i * 8;
        float4 f0 = *(const float4*)(prev + off);
        float4 f1 = *(const float4*)(prev + off + 4);
        *(__half2*)(g_prevh + off + 0) = __floats2half2_rn(f0.x, f0.y);
        *(__half2*)(g_prevh + off + 2) = __floats2half2_rn(f0.z, f0.w);
        *(__half2*)(g_prevh + off + 4) = __floats2half2_rn(f1.x, f1.y);
        *(__half2*)(g_prevh + off + 6) = __floats2half2_rn(f1.z, f1.w);
    } else if (i < NP + NC) {
        size_t off = (i - NP) * 8;
        float4 f0 = *(const float4*)(cur + off);
        float4 f1 = *(const float4*)(cur + off + 4);
        __half2 h0 = __floats2half2_rn(f0.x, f0.y), h1 = __floats2half2_rn(f0.z, f0.w);
        __half2 h2 = __floats2half2_rn(f1.x, f1.y), h3 = __floats2half2_rn(f1.z, f1.w);
        *(__half2*)(g_curh + off + 0) = h0;  *(__half2*)(g_curh + off + 2) = h1;
        *(__half2*)(g_curh + off + 4) = h2;  *(__half2*)(g_curh + off + 6) = h3;
        size_t b = off >> 8, c = off & 255;        // 8 floats never cross a row
        __half* xd = g_xh + b * 512 + c;
        *(__half2*)(xd + 0) = h0;  *(__half2*)(xd + 2) = h1;
        *(__half2*)(xd + 4) = h2;  *(__half2*)(xd + 6) = h3;
    }
}

// ===========================================================================
// prep_weights: fp32 [K][256] -> fp16 k-paired: (k,n) at (k>>1)*512 + n*2 + (k&1)
// slots: 0..3 = Wz/Wr/Wh top + Wq; 4..6 = Wz/Wr/Wh bottom; 7 = Wk; 8 = Wo (K=512)
// ===========================================================================
__global__ __launch_bounds__(256)
void prep_weights(const float* __restrict__ Wz, const float* __restrict__ Wr,
                  const float* __restrict__ Wh, const float* __restrict__ Wq,
                  const float* __restrict__ Wk, const float* __restrict__ Wo)
{
    const int blk = blockIdx.z;
    const float* src; size_t slot; int K;
    switch (blk) {
        case 0: src = Wz;         slot = 0; K = 256; break;
        case 1: src = Wr;         slot = 1; K = 256; break;
        case 2: src = Wh;         slot = 2; K = 256; break;
        case 3: src = Wq;         slot = 3; K = 256; break;
        case 4: src = Wz + 65536; slot = 4; K = 256; break;
        case 5: src = Wr + 65536; slot = 5; K = 256; break;
        case 6: src = Wh + 65536; slot = 6; K = 256; break;
        case 7: src = Wk;         slot = 7; K = 256; break;
        default: src = Wo;        slot = 8; K = 512; break;
    }
    int n = blockIdx.x * 32 + (threadIdx.x & 31);
    int k = blockIdx.y * 8 + (threadIdx.x >> 5);
    if (k >= K) return;
    g_w16[slot * 65536 + (size_t)(k >> 1) * 512 + n * 2 + (k & 1)] =
        __float2half(src[(size_t)k * 256 + n]);
}

// ===========================================================================
// fp16 tensor-core GEMM, 128x128 CTA tile, 256 threads (8 warps, 2m x 4n),
// warp tile 64x32, mma m16n8k16. K chunks of 64, triple-buffered cp.async,
// one barrier per chunk. 2 CTAs/SM.  (round-12 proven engine)
// MODE 0: curx = cur @ Wseg + bias         -> g_curxh   (K=256, 4 segs)
// MODE 1: seg0: z; seg1: rp                -> g_zh,g_rph(K=256)
// MODE 2: cand/GRU                         -> out + g_updh (K=256)
// MODE 3: scores = (upd@Wk + bk).q         -> g_scores  (K=256)
// MODE 4: f = x @ Wo + bo                  -> g_f       (K=512)
// ===========================================================================
#define AH2 36
#define BH2 136
#define A_H2 (128 * AH2)
#define B_H2c (32 * BH2)
#define BUF_H2 (A_H2 + B_H2c)
#define GEMM_SMEM (3 * BUF_H2 * 4)

template<int MODE>
__global__ __launch_bounds__(256, 2)
void mma_gemm(const float* __restrict__ ba, const float* __restrict__ bb,
              const float* __restrict__ bc, const float* __restrict__ bd,
              float* __restrict__ out)
{
    extern __shared__ __align__(16) uint32_t smh[];   // half2 units

    constexpr int KCH = (MODE == 4) ? 8 : 4;          // 64-wide K chunks
    constexpr int LDA = (MODE == 4) ? 512 : 256;

    const int tid  = threadIdx.x;
    const int lane = tid & 31;
    const int warp = tid >> 5;
    const int wm   = warp >> 2;           // 0..1
    const int wn   = warp & 3;            // 0..3
    const int q    = lane >> 2;           // 0..7
    const int t4   = lane & 3;            // 0..3

    const int n0  = blockIdx.x * 128;
    const int m0  = blockIdx.y * 128;
    const int seg = n0 >> 8;
    const int ncol = n0 & 255;

    const __half* Ap = (MODE == 0) ? g_curh : (MODE == 1) ? g_prevh
                     : (MODE == 2) ? g_rph  : (MODE == 3) ? g_updh : g_xh;
    const int slot = (MODE == 0) ? seg : (MODE == 1) ? 4 + seg
                   : (MODE == 2) ? 6 : (MODE == 3) ? 7 : 8;
    const __half* Wsrc = g_w16 + (size_t)slot * 65536;
    const float* bias = (seg == 0) ? ba : (seg == 1) ? bb : (seg == 2) ? bc : bd;

    float acc[4][4][4];
    #pragma unroll
    for (int i = 0; i < 4; i++)
        #pragma unroll
        for (int j = 0; j < 4; j++)
            #pragma unroll
            for (int v = 0; v < 4; v++) acc[i][j][v] = 0.f;

    auto load_chunk = [&](int bi, int k0) {
        uint32_t* Ad = smh + bi * BUF_H2;
        uint32_t* Bd = Ad + A_H2;
        #pragma unroll
        for (int i = 0; i < 4; i++) {               // A: 128x64 halves = 1024 granules
            int g = i * 256 + tid;
            int m = g >> 3, c8 = g & 7;
            cp_async16(smem_u32(Ad + m * AH2 + c8 * 4),
                       Ap + (size_t)(m0 + m) * LDA + k0 + c8 * 8);
        }
        #pragma unroll
        for (int i = 0; i < 4; i++) {               // B: 32 h2-rows x 128 n
            int g = i * 256 + tid;
            int k2 = g >> 5, n4 = (g & 31) << 2;
            cp_async16(smem_u32(Bd + k2 * BH2 + n4),
                       Wsrc + ((size_t)(k0 >> 1) + k2) * 512 + (ncol + n4) * 2);
        }
        cp_commit();
    };

    load_chunk(0, 0);
    load_chunk(1, 64);

    #pragma unroll
    for (int c = 0; c < KCH; c++) {
        if (c < KCH - 1) cp_wait<1>(); else cp_wait<0>();
        __syncthreads();
        if (c + 2 < KCH) load_chunk((c + 2) % 3, (c + 2) * 64);

        const uint32_t* Ah = smh + (c % 3) * BUF_H2;
        const uint32_t* Bh = Ah + A_H2;
        #pragma unroll
        for (int kk = 0; kk < 4; kk++) {            // 4 k16 steps per chunk
            uint32_t a[4][4], b[4][2];
            const int ac = kk * 8 + t4;
            #pragma unroll
            for (int mt = 0; mt < 4; mt++) {
                const int r0 = wm * 64 + mt * 16 + q;
                a[mt][0] = Ah[r0 * AH2 + ac];
                a[mt][1] = Ah[(r0 + 8) * AH2 + ac];
                a[mt][2] = Ah[r0 * AH2 + ac + 4];
                a[mt][3] = Ah[(r0 + 8) * AH2 + ac + 4];
            }
            #pragma unroll
            for (int nt = 0; nt < 4; nt++) {
                const int nb = wn * 32 + nt * 8 + q;
                b[nt][0] = Bh[ac * BH2 + nb];
                b[nt][1] = Bh[(ac + 4) * BH2 + nb];
            }
            #pragma unroll
            for (int mt = 0; mt < 4; mt++)
                #pragma unroll
                for (int nt = 0; nt < 4; nt++)
                    mma_f16(acc[mt][nt], a[mt], b[nt]);
        }
    }

    // ---------------- epilogue ----------------
    if (MODE == 3) {
        const int head = (n0 >> 5) + wn;
        #pragma unroll
        for (int mt = 0; mt < 4; mt++) {
            #pragma unroll
            for (int half = 0; half < 2; half++) {
                const int row = m0 + wm * 64 + mt * 16 + q + half * 8;
                const int b = row / 10, m = row - b * 10;
                const __half* qp = g_curxh + (size_t)b * 1024 + 768;
                float s = 0.f;
                #pragma unroll
                for (int nt = 0; nt < 4; nt++) {
                    const int col = n0 + wn * 32 + nt * 8 + 2 * t4;
                    float2 bk2 = *(const float2*)(ba + col);
                    float2 qv  = h2f(*(const __half2*)(qp + col));
                    s += (acc[mt][nt][half * 2 + 0] + bk2.x) * qv.x
                       + (acc[mt][nt][half * 2 + 1] + bk2.y) * qv.y;
                }
                s += __shfl_xor_sync(0xffffffffu, s, 1);
                s += __shfl_xor_sync(0xffffffffu, s, 2);
                if (t4 == 0)
                    g_scores[((size_t)b * 8 + head) * 10 + m] = s;
            }
        }
        return;
    }

    #pragma unroll
    for (int mt = 0; mt < 4; mt++) {
        #pragma unroll
        for (int nt = 0; nt < 4; nt++) {
            const int h = ncol + wn * 32 + nt * 8 + 2 * t4;   // within 256-seg
            #pragma unroll
            for (int half = 0; half < 2; half++) {
                const int row = m0 + wm * 64 + mt * 16 + q + half * 8;
                const float v0 = acc[mt][nt][half * 2 + 0];
                const float v1 = acc[mt][nt][half * 2 + 1];
                if (MODE == 0) {
                    float2 bb2 = *(const float2*)(bias + h);
                    *(__half2*)(g_curxh + (size_t)row * 1024 + seg * 256 + h) =
                        __floats2half2_rn(v0 + bb2.x, v1 + bb2.y);
                } else if (MODE == 1) {
                    const int b = row / 10;
                    if (seg == 0) {
                        float2 cx = h2f(*(const __half2*)(g_curxh + (size_t)b * 1024 + h));
                        *(__half2*)(g_zh + (size_t)row * 256 + h) =
                            __floats2half2_rn(sigmoidf_(v0 + cx.x), sigmoidf_(v1 + cx.y));
                    } else {
                        float2 cx = h2f(*(const __half2*)(g_curxh + (size_t)b * 1024 + 256 + h));
                        float2 pv = h2f(*(const __half2*)(g_prevh + (size_t)row * 256 + h));
                        *(__half2*)(g_rph + (size_t)row * 256 + h) =
                            __floats2half2_rn(sigmoidf_(v0 + cx.x) * pv.x,
                                              sigmoidf_(v1 + cx.y) * pv.y);
                    }
                } else if (MODE == 2) {
                    const int b = row / 10;
                    float2 cx = h2f(*(const __half2*)(g_curxh + (size_t)b * 1024 + 512 + h));
                    float2 zz = h2f(*(const __half2*)(g_zh + (size_t)row * 256 + h));
                    float2 pv = h2f(*(const __half2*)(g_prevh + (size_t)row * 256 + h));
                    float c0 = tanhf_(v0 + cx.x), c1 = tanhf_(v1 + cx.y);
                    float u0 = (1.f - zz.x) * pv.x + zz.x * c0;
                    float u1 = (1.f - zz.y) * pv.y + zz.y * c1;
                    *(float2*)(out + (size_t)row * 256 + h) = make_float2(u0, u1);
                    *(__half2*)(g_updh + (size_t)row * 256 + h) = __floats2half2_rn(u0, u1);
                } else {  // MODE 4
                    float2 bb2 = *(const float2*)(ba + h);
                    *(float2*)(g_f + (size_t)row * 256 + h) =
                        make_float2(v0 + bb2.x, v1 + bb2.y);
                }
            }
        }
    }
}

// ---------------------------------------------------------------------------
// attn_light: softmax + head-mean over g_scores, weighted memory (fp16 reads),
// fill weighted half of g_xh. GB=32 batches/CTA.
// ---------------------------------------------------------------------------
#define GB_ 32

__global__ __launch_bounds__(256)
void attn_light(float* __restrict__ d_out)
{
    __shared__ float ss[GB_ * 80];
    __shared__ float sattn[GB_ * 10];

    const int tid = threadIdx.x;
    const int b0 = blockIdx.x * GB_;
    float* attn_out = d_out + (size_t)B_ * 256 + (size_t)BM_ * 256;

    const float scale = 0.17677669529663687f;
    for (int t = tid; t < GB_ * 80; t += 256)
        ss[t] = g_scores[(size_t)b0 * 80 + t] * scale;
    __syncthreads();

    for (int t = tid; t < GB_ * 8; t += 256) {
        float* row = ss + t * 10;
        float mx = row[0];
        #pragma unroll
        for (int m = 1; m < 10; m++) mx = fmaxf(mx, row[m]);
        float e[10], sum = 0.f;
        #pragma unroll
        for (int m = 0; m < 10; m++) { e[m] = __expf(row[m] - mx); sum += e[m]; }
        float inv = __fdividef(1.f, sum);
        #pragma unroll
        for (int m = 0; m < 10; m++) row[m] = e[m] * inv;
    }
    __syncthreads();

    for (int t = tid; t < GB_ * 10; t += 256) {
        int bi = t / 10, m = t % 10;
        float s = 0.f;
        #pragma unroll
        for (int n = 0; n < 8; n++) s += ss[(bi * 8 + n) * 10 + m];
        s *= 0.125f;
        sattn[t] = s;
        attn_out[(size_t)(b0 + bi) * 10 + m] = s;
    }
    __syncthreads();

    for (int idx = tid; idx < GB_ * 32; idx += 256) {
        int bi = idx >> 5, g8 = idx & 31;
        const __half2* up = (const __half2*)(g_updh + ((size_t)(b0 + bi) * 10) * 256) + g8 * 4;
        const float* aw = sattn + bi * 10;
        float2 s0 = {0.f, 0.f}, s1 = {0.f, 0.f}, s2 = {0.f, 0.f}, s3 = {0.f, 0.f};
        #pragma unroll
        for (int m = 0; m < 10; m++) {
            float w = aw[m];
            float2 u0 = h2f(up[m * 128 + 0]);
            float2 u1 = h2f(up[m * 128 + 1]);
            float2 u2 = h2f(up[m * 128 + 2]);
            float2 u3 = h2f(up[m * 128 + 3]);
            s0.x += u0.x * w; s0.y += u0.y * w;
            s1.x += u1.x * w; s1.y += u1.y * w;
            s2.x += u2.x * w; s2.y += u2.y * w;
            s3.x += u3.x * w; s3.y += u3.y * w;
        }
        __half2* xw = (__half2*)(g_xh + (size_t)(b0 + bi) * 512 + 256) + g8 * 4;
        xw[0] = __floats2half2_rn(s0.x, s0.y);
        xw[1] = __floats2half2_rn(s1.x, s1.y);
        xw[2] = __floats2half2_rn(s2.x, s2.y);
        xw[3] = __floats2half2_rn(s3.x, s3.y);
    }
}

// ---------------------------------------------------------------------------
// LayerNorm over g_f -> d_out. One warp per row, 8 rows/CTA.
// ---------------------------------------------------------------------------
__global__ __launch_bounds__(256)
void ln_kernel(const float* __restrict__ gamma, const float* __restrict__ beta,
               float* __restrict__ d_out)
{
    const int warp = threadIdx.x >> 5;
    const int lane = threadIdx.x & 31;
    const int row  = blockIdx.x * 8 + warp;

    float v[8], sum = 0.f;
    const float* src = g_f + (size_t)row * 256;
    #pragma unroll
    for (int i = 0; i < 8; i++) { v[i] = src[lane + 32 * i]; sum += v[i]; }
    #pragma unroll
    for (int o = 16; o > 0; o >>= 1) sum += __shfl_xor_sync(0xffffffffu, sum, o);
    float mu = sum * (1.f / 256.f);
    float sq = 0.f;
    #pragma unroll
    for (int i = 0; i < 8; i++) { float d = v[i] - mu; sq += d * d; }
    #pragma unroll
    for (int o = 16; o > 0; o >>= 1) sq += __shfl_xor_sync(0xffffffffu, sq, o);
    float rstd = rsqrtf(sq * (1.f / 256.f) + 1e-5f);
    float* dst = d_out + (size_t)row * 256;
    #pragma unroll
    for (int i = 0; i < 8; i++) {
        int d_ = lane + 32 * i;
        dst[d_] = (v[i] - mu) * rstd * gamma[d_] + beta[d_];
    }
}

extern "C" void kernel_launch(void* const* d_in, const int* in_sizes, int n_in,
                              void* d_out, int out_size)
{
    (void)in_sizes; (void)n_in; (void)out_size;
    const float* cur    = (const float*)d_in[0];
    const float* prev   = (const float*)d_in[1];
    const float* Wz     = (const float*)d_in[2];
    const float* bz     = (const float*)d_in[3];
    const float* Wr     = (const float*)d_in[4];
    const float* br     = (const float*)d_in[5];
    const float* Wh     = (const float*)d_in[6];
    const float* bh     = (const float*)d_in[7];
    const float* Wq     = (const float*)d_in[8];
    const float* bq     = (const float*)d_in[9];
    const float* Wk     = (const float*)d_in[10];
    const float* bk     = (const float*)d_in[11];
    const float* Wo     = (const float*)d_in[12];
    const float* bo     = (const float*)d_in[13];
    const float* gamma2 = (const float*)d_in[14];
    const float* beta2  = (const float*)d_in[15];
    float* out = (float*)d_out;
    float* upd = out + (size_t)B_ * 256;

    cudaFuncSetAttribute(mma_gemm<0>, cudaFuncAttributeMaxDynamicSharedMemorySize, (int)GEMM_SMEM);
    cudaFuncSetAttribute(mma_gemm<1>, cudaFuncAttributeMaxDynamicSharedMemorySize, (int)GEMM_SMEM);
    cudaFuncSetAttribute(mma_gemm<2>, cudaFuncAttributeMaxDynamicSharedMemorySize, (int)GEMM_SMEM);
    cudaFuncSetAttribute(mma_gemm<3>, cudaFuncAttributeMaxDynamicSharedMemorySize, (int)GEMM_SMEM);
    cudaFuncSetAttribute(mma_gemm<4>, cudaFuncAttributeMaxDynamicSharedMemorySize, (int)GEMM_SMEM);

    dim3 blk(256);
    const int NPREP = (int)(((size_t)BM_ * 256 / 8 + (size_t)B_ * 256 / 8 + 255) / 256);
    // 0) convert inputs + weights to fp16
    prep_inputs<<<NPREP, blk>>>(prev, cur);
    prep_weights<<<dim3(8, 64, 9), blk>>>(Wz, Wr, Wh, Wq, Wk, Wo);
    // 1) cur projections: [B,256] @ [256,1024]
    mma_gemm<0><<<dim3(8, B_ / 128), blk, GEMM_SMEM>>>(bz, br, bh, bq, nullptr);
    // 2) z/r gates: [BM,256] @ [256,512]
    mma_gemm<1><<<dim3(4, BM_ / 128), blk, GEMM_SMEM>>>(nullptr, nullptr, nullptr, nullptr, nullptr);
    // 3) cand + GRU update -> updated_memory (+ fp16 copy)
    mma_gemm<2><<<dim3(2, BM_ / 128), blk, GEMM_SMEM>>>(nullptr, nullptr, nullptr, nullptr, upd);
    // 4) k projection + fused attention scores -> g_scores
    mma_gemm<3><<<dim3(2, BM_ / 128), blk, GEMM_SMEM>>>(bk, nullptr, nullptr, nullptr, nullptr);
    // 5) softmax/head-mean/weighted -> g_xh, attn weights
    attn_light<<<dim3(B_ / GB_), blk>>>(out);
    // 6) output projection: [B,512] @ [512,256] -> g_f
    mma_gemm<4><<<dim3(2, B_ / 128), blk, GEMM_SMEM>>>(bo, nullptr, nullptr, nullptr, nullptr);
    // 7) LayerNorm -> d_out
    ln_kernel<<<dim3(B_ / 8), blk>>>(gamma2, beta2, out);
}

// round 15
// speedup vs baseline: 1.2347x; 1.0076x over previous
#include <cuda_runtime.h>
#include <cuda_fp16.h>
#include <math.h>
#include <stdint.h>

#define B_ 32768
#define M_ 10
#define BM_ (B_*M_)

// fp16 scratch (allocation-free rule: __device__ globals)
__device__ __align__(128) __half g_prevh[(size_t)BM_ * 256];
__device__ __align__(128) __half g_curh [(size_t)B_ * 256];
__device__ __align__(128) __half g_w16  [655360];            // W^T slots: 8 x [256n][256k] + Wo [256n][512k]
__device__ __align__(128) __half g_curxh[(size_t)B_ * 1024]; // [z|r|h|q] pre-acts per batch
__device__ __align__(128) __half g_zh   [(size_t)BM_ * 256];
__device__ __align__(128) __half g_rph  [(size_t)BM_ * 256];
__device__ __align__(128) __half g_updh [(size_t)BM_ * 256];
__device__ __align__(128) __half g_xh   [(size_t)B_ * 512];  // [cur | weighted]
__device__ float g_scores[(size_t)B_ * 80];
__device__ float g_f[(size_t)B_ * 256];

// fast-math activations (MUFU-based)
__device__ __forceinline__ float sigmoidf_(float x) {
    return __fdividef(1.f, 1.f + __expf(-x));
}
__device__ __forceinline__ float tanhf_(float x) {
    float t = __expf(-2.f * fabsf(x));
    float r = __fdividef(1.f - t, 1.f + t);
    return copysignf(r, x);
}
__device__ __forceinline__ float2 h2f(__half2 h) { return __half22float2(h); }

__device__ __forceinline__ uint32_t smem_u32(const void* p) {
    return (uint32_t)__cvta_generic_to_shared(p);
}
__device__ __forceinline__ void cp_async16(uint32_t s, const void* g) {
    asm volatile("cp.async.cg.shared.global [%0], [%1], 16;\n" :: "r"(s), "l"(g));
}
__device__ __forceinline__ void cp_commit() {
    asm volatile("cp.async.commit_group;\n");
}
template<int N>
__device__ __forceinline__ void cp_wait() {
    asm volatile("cp.async.wait_group %0;\n" :: "n"(N));
}
__device__ __forceinline__ void ldsm_x4(uint32_t& r0, uint32_t& r1, uint32_t& r2, uint32_t& r3,
                                        uint32_t addr) {
    asm volatile("ldmatrix.sync.aligned.m8n8.x4.shared.b16 {%0,%1,%2,%3}, [%4];"
                 : "=r"(r0), "=r"(r1), "=r"(r2), "=r"(r3) : "r"(addr));
}
__device__ __forceinline__ void mma_f16(float c[4], const uint32_t a[4], const uint32_t b[2]) {
    asm volatile(
        "mma.sync.aligned.m16n8k16.row.col.f32.f16.f16.f32 "
        "{%0,%1,%2,%3}, {%4,%5,%6,%7}, {%8,%9}, {%0,%1,%2,%3};"
        : "+f"(c[0]), "+f"(c[1]), "+f"(c[2]), "+f"(c[3])
        : "r"(a[0]), "r"(a[1]), "r"(a[2]), "r"(a[3]), "r"(b[0]), "r"(b[1]));
}

// ===========================================================================
// prep_inputs: prev, cur -> fp16; also seed g_xh cur-section.
// ===========================================================================
__global__ __launch_bounds__(256)
void prep_inputs(const float* __restrict__ prev, const float* __restrict__ cur)
{
    const size_t NP = (size_t)BM_ * 256 / 8;
    const size_t NC = (size_t)B_ * 256 / 8;
    size_t i = (size_t)blockIdx.x * 256 + threadIdx.x;
    if (i < NP) {
        size_t off = i * 8;
        float4 f0 = *(const float4*)(prev + off);
        float4 f1 = *(const float4*)(prev + off + 4);
        *(__half2*)(g_prevh + off + 0) = __floats2half2_rn(f0.x, f0.y);
        *(__half2*)(g_prevh + off + 2) = __floats2half2_rn(f0.z, f0.w);
        *(__half2*)(g_prevh + off + 4) = __floats2half2_rn(f1.x, f1.y);
        *(__half2*)(g_prevh + off + 6) = __floats2half2_rn(f1.z, f1.w);
    } else if (i < NP + NC) {
        size_t off = (i - NP) * 8;
        float4 f0 = *(const float4*)(cur + off);
        float4 f1 = *(const float4*)(cur + off + 4);
        __half2 h0 = __floats2half2_rn(f0.x, f0.y), h1 = __floats2half2_rn(f0.z, f0.w);
        __half2 h2 = __floats2half2_rn(f1.x, f1.y), h3 = __floats2half2_rn(f1.z, f1.w);
        *(__half2*)(g_curh + off + 0) = h0;  *(__half2*)(g_curh + off + 2) = h1;
        *(__half2*)(g_curh + off + 4) = h2;  *(__half2*)(g_curh + off + 6) = h3;
        size_t b = off >> 8, c = off & 255;
        __half* xd = g_xh + b * 512 + c;
        *(__half2*)(xd + 0) = h0;  *(__half2*)(xd + 2) = h1;
        *(__half2*)(xd + 4) = h2;  *(__half2*)(xd + 6) = h3;
    }
}

// ===========================================================================
// prep_weights: fp32 W[K][256] -> fp16 W^T[n][k].
// slots: 0..3 = Wz/Wr/Wh top + Wq; 4..6 = bottoms; 7 = Wk (K=256); 8 = Wo (K=512)
// ===========================================================================
__global__ __launch_bounds__(256)
void prep_weights(const float* __restrict__ Wz, const float* __restrict__ Wr,
                  const float* __restrict__ Wh, const float* __restrict__ Wq,
                  const float* __restrict__ Wk, const float* __restrict__ Wo)
{
    const int blk = blockIdx.z;
    const float* src; size_t slot; int K;
    switch (blk) {
        case 0: src = Wz;         slot = 0; K = 256; break;
        case 1: src = Wr;         slot = 1; K = 256; break;
        case 2: src = Wh;         slot = 2; K = 256; break;
        case 3: src = Wq;         slot = 3; K = 256; break;
        case 4: src = Wz + 65536; slot = 4; K = 256; break;
        case 5: src = Wr + 65536; slot = 5; K = 256; break;
        case 6: src = Wh + 65536; slot = 6; K = 256; break;
        case 7: src = Wk;         slot = 7; K = 256; break;
        default: src = Wo;        slot = 8; K = 512; break;
    }
    __shared__ float t[32][33];
    const int tx = threadIdx.x & 31, ty = threadIdx.x >> 5;
    const int n0 = blockIdx.x * 32, k0 = blockIdx.y * 32;
    if (k0 >= K) return;
    #pragma unroll
    for (int r = 0; r < 4; r++)
        t[ty + 8 * r][tx] = src[(size_t)(k0 + ty + 8 * r) * 256 + n0 + tx];
    __syncthreads();
    __half* dst = g_w16 + slot * 65536;
    #pragma unroll
    for (int r = 0; r < 4; r++)
        dst[(size_t)(n0 + ty + 8 * r) * K + k0 + tx] = __float2half(t[tx][ty + 8 * r]);
}

// ===========================================================================
// fp16 GEMM: 128x128 CTA tile, 256 threads (8 warps, 2m x 4n), warp tile 64x32,
// mma m16n8k16, ldmatrix fragment loads (A row-major [m][k], B = W^T [n][k]).
// K chunks of 64, triple-buffered cp.async, one barrier per chunk, 2 CTAs/SM.
// Smem tiles: 128 rows x 144 B (64 halves + 8 pad) each for A and B.
// ===========================================================================
#define ROWB 144                          // bytes per smem row
#define TILE_B (128 * ROWB)               // 18432 B per tile
#define BUF_B (2 * TILE_B)                // A + B per chunk
#define GEMM_SMEM (3 * BUF_B)             // 110592 B

template<int MODE>
__global__ __launch_bounds__(256, 2)
void mma_gemm(const float* __restrict__ ba, const float* __restrict__ bb,
              const float* __restrict__ bc, const float* __restrict__ bd,
              float* __restrict__ out)
{
    extern __shared__ __align__(16) char smc[];

    constexpr int KCH = (MODE == 4) ? 8 : 4;          // 64-wide K chunks
    constexpr int LDA = (MODE == 4) ? 512 : 256;      // A row length (halves)
    constexpr int LDW = (MODE == 4) ? 512 : 256;      // W^T row length (halves)

    const int tid  = threadIdx.x;
    const int lane = tid & 31;
    const int warp = tid >> 5;
    const int wm   = warp >> 2;           // 0..1
    const int wn   = warp & 3;            // 0..3
    const int q    = lane >> 2;           // 0..7
    const int t4   = lane & 3;            // 0..3
    const int mi   = lane >> 3;           // ldmatrix matrix index 0..3
    const int mr   = lane & 7;            // ldmatrix row within matrix

    const int n0  = blockIdx.x * 128;
    const int m0  = blockIdx.y * 128;
    const int seg = n0 >> 8;
    const int ncol = n0 & 255;

    const __half* Ap = (MODE == 0) ? g_curh : (MODE == 1) ? g_prevh
                     : (MODE == 2) ? g_rph  : (MODE == 3) ? g_updh : g_xh;
    const int slot = (MODE == 0) ? seg : (MODE == 1) ? 4 + seg
                   : (MODE == 2) ? 6 : (MODE == 3) ? 7 : 8;
    const __half* Wt = g_w16 + (size_t)slot * 65536;
    const float* bias = (seg == 0) ? ba : (seg == 1) ? bb : (seg == 2) ? bc : bd;

    const uint32_t sb = smem_u32(smc);

    float acc[4][4][4];
    #pragma unroll
    for (int i = 0; i < 4; i++)
        #pragma unroll
        for (int j = 0; j < 4; j++)
            #pragma unroll
            for (int v = 0; v < 4; v++) acc[i][j][v] = 0.f;

    auto load_chunk = [&](int bi, int k0) {
        uint32_t base = sb + bi * BUF_B;
        #pragma unroll
        for (int i = 0; i < 4; i++) {               // A: 128 rows x 8 granules
            int g = i * 256 + tid;
            int m = g >> 3, gr = g & 7;
            cp_async16(base + m * ROWB + gr * 16,
                       Ap + (size_t)(m0 + m) * LDA + k0 + gr * 8);
        }
        #pragma unroll
        for (int i = 0; i < 4; i++) {               // B: 128 n-rows x 8 granules
            int g = i * 256 + tid;
            int n = g >> 3, gr = g & 7;
            cp_async16(base + TILE_B + n * ROWB + gr * 16,
                       Wt + (size_t)(ncol + n) * LDW + k0 + gr * 8);
        }
        cp_commit();
    };

    load_chunk(0, 0);
    load_chunk(1, 64);

    // per-thread ldmatrix base offsets (within a buffer)
    const uint32_t aOff = (uint32_t)((wm * 64 + (mi & 1) * 8 + mr) * ROWB + (mi >> 1) * 16);
    const uint32_t bOff = (uint32_t)(TILE_B + (wn * 32 + (mi >> 1) * 8 + mr) * ROWB + (mi & 1) * 16);

    #pragma unroll
    for (int c = 0; c < KCH; c++) {
        if (c < KCH - 1) cp_wait<1>(); else cp_wait<0>();
        __syncthreads();
        if (c + 2 < KCH) load_chunk((c + 2) % 3, (c + 2) * 64);

        const uint32_t bufA = sb + (c % 3) * BUF_B + aOff;
        const uint32_t bufB = sb + (c % 3) * BUF_B + bOff;
        #pragma unroll
        for (int kk = 0; kk < 4; kk++) {            // 4 k16 steps per 64-k chunk
            uint32_t a[4][4], b[4][2];
            #pragma unroll
            for (int mt = 0; mt < 4; mt++)
                ldsm_x4(a[mt][0], a[mt][1], a[mt][2], a[mt][3],
                        bufA + mt * (16 * ROWB) + kk * 32);
            ldsm_x4(b[0][0], b[0][1], b[1][0], b[1][1], bufB + kk * 32);
            ldsm_x4(b[2][0], b[2][1], b[3][0], b[3][1], bufB + 16 * ROWB + kk * 32);
            #pragma unroll
            for (int mt = 0; mt < 4; mt++)
                #pragma unroll
                for (int nt = 0; nt < 4; nt++)
                    mma_f16(acc[mt][nt], a[mt], b[nt]);
        }
    }

    // ---------------- epilogue ----------------
    if (MODE == 3) {
        const int head = (n0 >> 5) + wn;
        #pragma unroll
        for (int mt = 0; mt < 4; mt++) {
            #pragma unroll
            for (int half = 0; half < 2; half++) {
                const int row = m0 + wm * 64 + mt * 16 + q + half * 8;
                const int b = row / 10, m = row - b * 10;
                const __half* qp = g_curxh + (size_t)b * 1024 + 768;
                float s = 0.f;
                #pragma unroll
                for (int nt = 0; nt < 4; nt++) {
                    const int col = n0 + wn * 32 + nt * 8 + 2 * t4;
                    float2 bk2 = *(const float2*)(ba + col);
                    float2 qv  = h2f(*(const __half2*)(qp + col));
                    s += (acc[mt][nt][half * 2 + 0] + bk2.x) * qv.x
                       + (acc[mt][nt][half * 2 + 1] + bk2.y) * qv.y;
                }
                s += __shfl_xor_sync(0xffffffffu, s, 1);
                s += __shfl_xor_sync(0xffffffffu, s, 2);
                if (t4 == 0)
                    g_scores[((size_t)b * 8 + head) * 10 + m] = s;
            }
        }
        return;
    }

    #pragma unroll
    for (int mt = 0; mt < 4; mt++) {
        #pragma unroll
        for (int nt = 0; nt < 4; nt++) {
            const int h = ncol + wn * 32 + nt * 8 + 2 * t4;
            #pragma unroll
            for (int half = 0; half < 2; half++) {
                const int row = m0 + wm * 64 + mt * 16 + q + half * 8;
                const float v0 = acc[mt][nt][half * 2 + 0];
                const float v1 = acc[mt][nt][half * 2 + 1];
                if (MODE == 0) {
                    float2 bb2 = *(const float2*)(bias + h);
                    *(__half2*)(g_curxh + (size_t)row * 1024 + seg * 256 + h) =
                        __floats2half2_rn(v0 + bb2.x, v1 + bb2.y);
                } else if (MODE == 1) {
                    const int b = row / 10;
                    if (seg == 0) {
                        float2 cx = h2f(*(const __half2*)(g_curxh + (size_t)b * 1024 + h));
                        *(__half2*)(g_zh + (size_t)row * 256 + h) =
                            __floats2half2_rn(sigmoidf_(v0 + cx.x), sigmoidf_(v1 + cx.y));
                    } else {
                        float2 cx = h2f(*(const __half2*)(g_curxh + (size_t)b * 1024 + 256 + h));
                        float2 pv = h2f(*(const __half2*)(g_prevh + (size_t)row * 256 + h));
                        *(__half2*)(g_rph + (size_t)row * 256 + h) =
                            __floats2half2_rn(sigmoidf_(v0 + cx.x) * pv.x,
                                              sigmoidf_(v1 + cx.y) * pv.y);
                    }
                } else if (MODE == 2) {
                    const int b = row / 10;
                    float2 cx = h2f(*(const __half2*)(g_curxh + (size_t)b * 1024 + 512 + h));
                    float2 zz = h2f(*(const __half2*)(g_zh + (size_t)row * 256 + h));
                    float2 pv = h2f(*(const __half2*)(g_prevh + (size_t)row * 256 + h));
                    float c0 = tanhf_(v0 + cx.x), c1 = tanhf_(v1 + cx.y);
                    float u0 = (1.f - zz.x) * pv.x + zz.x * c0;
                    float u1 = (1.f - zz.y) * pv.y + zz.y * c1;
                    *(float2*)(out + (size_t)row * 256 + h) = make_float2(u0, u1);
                    *(__half2*)(g_updh + (size_t)row * 256 + h) = __floats2half2_rn(u0, u1);
                } else {  // MODE 4
                    float2 bb2 = *(const float2*)(ba + h);
                    *(float2*)(g_f + (size_t)row * 256 + h) =
                        make_float2(v0 + bb2.x, v1 + bb2.y);
                }
            }
        }
    }
}

// ---------------------------------------------------------------------------
// attn_light: softmax + head-mean over g_scores, weighted memory, fill g_xh.
// ---------------------------------------------------------------------------
#define GB_ 32

__global__ __launch_bounds__(256)
void attn_light(float* __restrict__ d_out)
{
    __shared__ float ss[GB_ * 80];
    __shared__ float sattn[GB_ * 10];

    const int tid = threadIdx.x;
    const int b0 = blockIdx.x * GB_;
    float* attn_out = d_out + (size_t)B_ * 256 + (size_t)BM_ * 256;

    const float scale = 0.17677669529663687f;
    for (int t = tid; t < GB_ * 80; t += 256)
        ss[t] = g_scores[(size_t)b0 * 80 + t] * scale;
    __syncthreads();

    for (int t = tid; t < GB_ * 8; t += 256) {
        float* row = ss + t * 10;
        float mx = row[0];
        #pragma unroll
        for (int m = 1; m < 10; m++) mx = fmaxf(mx, row[m]);
        float e[10], sum = 0.f;
        #pragma unroll
        for (int m = 0; m < 10; m++) { e[m] = __expf(row[m] - mx); sum += e[m]; }
        float inv = __fdividef(1.f, sum);
        #pragma unroll
        for (int m = 0; m < 10; m++) row[m] = e[m] * inv;
    }
    __syncthreads();

    for (int t = tid; t < GB_ * 10; t += 256) {
        int bi = t / 10, m = t % 10;
        float s = 0.f;
        #pragma unroll
        for (int n = 0; n < 8; n++) s += ss[(bi * 8 + n) * 10 + m];
        s *= 0.125f;
        sattn[t] = s;
        attn_out[(size_t)(b0 + bi) * 10 + m] = s;
    }
    __syncthreads();

    for (int idx = tid; idx < GB_ * 32; idx += 256) {
        int bi = idx >> 5, g8 = idx & 31;
        const __half2* up = (const __half2*)(g_updh + ((size_t)(b0 + bi) * 10) * 256) + g8 * 4;
        const float* aw = sattn + bi * 10;
        float2 s0 = {0.f, 0.f}, s1 = {0.f, 0.f}, s2 = {0.f, 0.f}, s3 = {0.f, 0.f};
        #pragma unroll
        for (int m = 0; m < 10; m++) {
            float w = aw[m];
            float2 u0 = h2f(up[m * 128 + 0]);
            float2 u1 = h2f(up[m * 128 + 1]);
            float2 u2 = h2f(up[m * 128 + 2]);
            float2 u3 = h2f(up[m * 128 + 3]);
            s0.x += u0.x * w; s0.y += u0.y * w;
            s1.x += u1.x * w; s1.y += u1.y * w;
            s2.x += u2.x * w; s2.y += u2.y * w;
            s3.x += u3.x * w; s3.y += u3.y * w;
        }
        __half2* xw = (__half2*)(g_xh + (size_t)(b0 + bi) * 512 + 256) + g8 * 4;
        xw[0] = __floats2half2_rn(s0.x, s0.y);
        xw[1] = __floats2half2_rn(s1.x, s1.y);
        xw[2] = __floats2half2_rn(s2.x, s2.y);
        xw[3] = __floats2half2_rn(s3.x, s3.y);
    }
}

// ---------------------------------------------------------------------------
// LayerNorm over g_f -> d_out.
// ---------------------------------------------------------------------------
__global__ __launch_bounds__(256)
void ln_kernel(const float* __restrict__ gamma, const float* __restrict__ beta,
               float* __restrict__ d_out)
{
    const int warp = threadIdx.x >> 5;
    const int lane = threadIdx.x & 31;
    const int row  = blockIdx.x * 8 + warp;

    float v[8], sum = 0.f;
    const float* src = g_f + (size_t)row * 256;
    #pragma unroll
    for (int i = 0; i < 8; i++) { v[i] = src[lane + 32 * i]; sum += v[i]; }
    #pragma unroll
    for (int o = 16; o > 0; o >>= 1) sum += __shfl_xor_sync(0xffffffffu, sum, o);
    float mu = sum * (1.f / 256.f);
    float sq = 0.f;
    #pragma unroll
    for (int i = 0; i < 8; i++) { float d = v[i] - mu; sq += d * d; }
    #pragma unroll
    for (int o = 16; o > 0; o >>= 1) sq += __shfl_xor_sync(0xffffffffu, sq, o);
    float rstd = rsqrtf(sq * (1.f / 256.f) + 1e-5f);
    float* dst = d_out + (size_t)row * 256;
    #pragma unroll
    for (int i = 0; i < 8; i++) {
        int d_ = lane + 32 * i;
        dst[d_] = (v[i] - mu) * rstd * gamma[d_] + beta[d_];
    }
}

extern "C" void kernel_launch(void* const* d_in, const int* in_sizes, int n_in,
                              void* d_out, int out_size)
{
    (void)in_sizes; (void)n_in; (void)out_size;
    const float* cur    = (const float*)d_in[0];
    const float* prev   = (const float*)d_in[1];
    const float* Wz     = (const float*)d_in[2];
    const float* bz     = (const float*)d_in[3];
    const float* Wr     = (const float*)d_in[4];
    const float* br     = (const float*)d_in[5];
    const float* Wh     = (const float*)d_in[6];
    const float* bh     = (const float*)d_in[7];
    const float* Wq     = (const float*)d_in[8];
    const float* bq     = (const float*)d_in[9];
    const float* Wk     = (const float*)d_in[10];
    const float* bk     = (const float*)d_in[11];
    const float* Wo     = (const float*)d_in[12];
    const float* bo     = (const float*)d_in[13];
    const float* gamma2 = (const float*)d_in[14];
    const float* beta2  = (const float*)d_in[15];
    float* out = (float*)d_out;
    float* upd = out + (size_t)B_ * 256;

    cudaFuncSetAttribute(mma_gemm<0>, cudaFuncAttributeMaxDynamicSharedMemorySize, (int)GEMM_SMEM);
    cudaFuncSetAttribute(mma_gemm<1>, cudaFuncAttributeMaxDynamicSharedMemorySize, (int)GEMM_SMEM);
    cudaFuncSetAttribute(mma_gemm<2>, cudaFuncAttributeMaxDynamicSharedMemorySize, (int)GEMM_SMEM);
    cudaFuncSetAttribute(mma_gemm<3>, cudaFuncAttributeMaxDynamicSharedMemorySize, (int)GEMM_SMEM);
    cudaFuncSetAttribute(mma_gemm<4>, cudaFuncAttributeMaxDynamicSharedMemorySize, (int)GEMM_SMEM);

    dim3 blk(256);
    const int NPREP = (int)(((size_t)BM_ * 256 / 8 + (size_t)B_ * 256 / 8 + 255) / 256);
    // 0) convert inputs; weights -> W^T fp16
    prep_inputs<<<NPREP, blk>>>(prev, cur);
    prep_weights<<<dim3(8, 16, 9), blk>>>(Wz, Wr, Wh, Wq, Wk, Wo);
    // 1) cur projections: [B,256] @ [256,1024]
    mma_gemm<0><<<dim3(8, B_ / 128), blk, GEMM_SMEM>>>(bz, br, bh, bq, nullptr);
    // 2) z/r gates: [BM,256] @ [256,512]
    mma_gemm<1><<<dim3(4, BM_ / 128), blk, GEMM_SMEM>>>(nullptr, nullptr, nullptr, nullptr, nullptr);
    // 3) cand + GRU update -> updated_memory (+ fp16 copy)
    mma_gemm<2><<<dim3(2, BM_ / 128), blk, GEMM_SMEM>>>(nullptr, nullptr, nullptr, nullptr, upd);
    // 4) k projection + fused attention scores -> g_scores
    mma_gemm<3><<<dim3(2, BM_ / 128), blk, GEMM_SMEM>>>(bk, nullptr, nullptr, nullptr, nullptr);
    // 5) softmax/head-mean/weighted -> g_xh, attn weights
    attn_light<<<dim3(B_ / GB_), blk>>>(out);
    // 6) output projection: [B,512] @ [512,256] -> g_f
    mma_gemm<4><<<dim3(2, B_ / 128), blk, GEMM_SMEM>>>(bo, nullptr, nullptr, nullptr, nullptr);
    // 7) LayerNorm -> d_out
    ln_kernel<<<dim3(B_ / 8), blk>>>(gamma2, beta2, out);
}